// round 1
// baseline (speedup 1.0000x reference)
#include <cuda_runtime.h>
#include <math.h>

#define NN 8192
#define HD 256

// Scratch (device globals: allocation-free rule).
static __device__ float g_fused[NN * HD];                 // 8 MB
static __device__ float g_hn[NN * HD];                    // 8 MB
static __device__ float g_sim[(size_t)NN * NN];           // 256 MB

// ---------------------------------------------------------------------------
// Encoder: one block computes a 128x128 tile of fused = sum_m relu(X_m W_m + b_m)
// (the /3 is deferred to the normalize kernel). 256 threads, 8x8 per thread,
// BK=8, double-buffered smem, FMA-bound.
// ---------------------------------------------------------------------------
__device__ __forceinline__ void enc_gemm_one(
    float (&total)[8][8],
    const float* __restrict__ X, const float* __restrict__ W,
    const float* __restrict__ bias,
    int K, int rowBase, int colBase, int tid,
    float (*As)[8][128], float (*Bs)[8][128])
{
    const int arow = tid >> 1;          // 0..127
    const int akx  = (tid & 1) * 4;     // 0 or 4
    const int bk   = tid >> 5;          // 0..7
    const int bn   = (tid & 31) * 4;    // 0..124
    const int ty   = tid >> 4;          // 0..15
    const int tx   = tid & 15;          // 0..15

    const float* aPtr = X + (size_t)(rowBase + arow) * K + akx;
    const float* bPtr = W + (size_t)bk * HD + colBase + bn;

    float acc[8][8];
    #pragma unroll
    for (int i = 0; i < 8; i++)
        #pragma unroll
        for (int j = 0; j < 8; j++) acc[i][j] = 0.0f;

    const int ntiles = K >> 3;

    float4 a4 = *(const float4*)aPtr;
    float4 b4 = *(const float4*)bPtr;
    As[0][akx + 0][arow] = a4.x; As[0][akx + 1][arow] = a4.y;
    As[0][akx + 2][arow] = a4.z; As[0][akx + 3][arow] = a4.w;
    *(float4*)&Bs[0][bk][bn] = b4;
    __syncthreads();

    for (int t = 0; t < ntiles; ++t) {
        const int cur = t & 1;
        if (t + 1 < ntiles) {
            a4 = *(const float4*)(aPtr + (t + 1) * 8);
            b4 = *(const float4*)(bPtr + (size_t)(t + 1) * 8 * HD);
        }
        #pragma unroll
        for (int kk = 0; kk < 8; kk++) {
            float4 A0 = *(const float4*)&As[cur][kk][ty * 8];
            float4 A1 = *(const float4*)&As[cur][kk][ty * 8 + 4];
            float4 B0 = *(const float4*)&Bs[cur][kk][tx * 8];
            float4 B1 = *(const float4*)&Bs[cur][kk][tx * 8 + 4];
            float ar[8] = {A0.x, A0.y, A0.z, A0.w, A1.x, A1.y, A1.z, A1.w};
            float br[8] = {B0.x, B0.y, B0.z, B0.w, B1.x, B1.y, B1.z, B1.w};
            #pragma unroll
            for (int i = 0; i < 8; i++)
                #pragma unroll
                for (int j = 0; j < 8; j++)
                    acc[i][j] = fmaf(ar[i], br[j], acc[i][j]);
        }
        if (t + 1 < ntiles) {
            const int nxt = cur ^ 1;
            As[nxt][akx + 0][arow] = a4.x; As[nxt][akx + 1][arow] = a4.y;
            As[nxt][akx + 2][arow] = a4.z; As[nxt][akx + 3][arow] = a4.w;
            *(float4*)&Bs[nxt][bk][bn] = b4;
        }
        __syncthreads();
    }

    const int col = colBase + tx * 8;
    float bb[8];
    #pragma unroll
    for (int j = 0; j < 8; j++) bb[j] = bias[col + j];
    #pragma unroll
    for (int i = 0; i < 8; i++)
        #pragma unroll
        for (int j = 0; j < 8; j++)
            total[i][j] += fmaxf(acc[i][j] + bb[j], 0.0f);
}

__global__ __launch_bounds__(256, 1)
void enc_kernel(const float* __restrict__ X0, const float* __restrict__ W0, const float* __restrict__ b0,
                const float* __restrict__ X1, const float* __restrict__ W1, const float* __restrict__ b1,
                const float* __restrict__ X2, const float* __restrict__ W2, const float* __restrict__ b2)
{
    __shared__ float As[2][8][128];
    __shared__ float Bs[2][8][128];
    const int tid = threadIdx.x;
    const int rowBase = blockIdx.y * 128;
    const int colBase = blockIdx.x * 128;

    float total[8][8];
    #pragma unroll
    for (int i = 0; i < 8; i++)
        #pragma unroll
        for (int j = 0; j < 8; j++) total[i][j] = 0.0f;

    // order matches reference: image + text + audio (left-associated)
    enc_gemm_one(total, X0, W0, b0, 1024, rowBase, colBase, tid, As, Bs);
    enc_gemm_one(total, X1, W1, b1,  768, rowBase, colBase, tid, As, Bs);
    enc_gemm_one(total, X2, W2, b2,  512, rowBase, colBase, tid, As, Bs);

    const int ty = tid >> 4, tx = tid & 15;
    const int row = rowBase + ty * 8;
    const int col = colBase + tx * 8;
    #pragma unroll
    for (int i = 0; i < 8; i++) {
        float4 o0 = make_float4(total[i][0], total[i][1], total[i][2], total[i][3]);
        float4 o1 = make_float4(total[i][4], total[i][5], total[i][6], total[i][7]);
        *(float4*)&g_fused[(size_t)(row + i) * HD + col]     = o0;
        *(float4*)&g_fused[(size_t)(row + i) * HD + col + 4] = o1;
    }
}

// ---------------------------------------------------------------------------
// Row normalize: hn = (fused/3) / (||fused/3|| + 1e-8). One warp per row.
// ---------------------------------------------------------------------------
__global__ void norm_kernel()
{
    const int tid  = threadIdx.x;
    const int lane = tid & 31;
    const int warp = tid >> 5;
    const int row  = blockIdx.x * 8 + warp;

    const float* fr = g_fused + (size_t)row * HD;
    float v[8];
    float ss = 0.0f;
    #pragma unroll
    for (int i = 0; i < 8; i++) {
        float x = fr[lane + i * 32] / 3.0f;
        v[i] = x;
        ss += x * x;
    }
    #pragma unroll
    for (int off = 16; off > 0; off >>= 1)
        ss += __shfl_xor_sync(0xffffffffu, ss, off);
    const float den = sqrtf(ss) + 1e-8f;
    #pragma unroll
    for (int i = 0; i < 8; i++)
        g_hn[(size_t)row * HD + lane + i * 32] = v[i] / den;
}

// ---------------------------------------------------------------------------
// sim = hn @ hn^T. Same 128x128 / 8x8 microkernel; both tiles loaded with the
// identical transposed-store pattern (B operand is rows of hn too).
// ---------------------------------------------------------------------------
__global__ __launch_bounds__(256, 2)
void sim_kernel()
{
    __shared__ float As[2][8][128];
    __shared__ float Bs[2][8][128];
    const int tid = threadIdx.x;
    const int rowBase = blockIdx.y * 128;
    const int colBase = blockIdx.x * 128;
    const int arow = tid >> 1;
    const int akx  = (tid & 1) * 4;
    const int ty   = tid >> 4;
    const int tx   = tid & 15;

    const float* aPtr = g_hn + (size_t)(rowBase + arow) * HD + akx;
    const float* bPtr = g_hn + (size_t)(colBase + arow) * HD + akx;

    float acc[8][8];
    #pragma unroll
    for (int i = 0; i < 8; i++)
        #pragma unroll
        for (int j = 0; j < 8; j++) acc[i][j] = 0.0f;

    float4 a4 = *(const float4*)aPtr;
    float4 b4 = *(const float4*)bPtr;
    As[0][akx + 0][arow] = a4.x; As[0][akx + 1][arow] = a4.y;
    As[0][akx + 2][arow] = a4.z; As[0][akx + 3][arow] = a4.w;
    Bs[0][akx + 0][arow] = b4.x; Bs[0][akx + 1][arow] = b4.y;
    Bs[0][akx + 2][arow] = b4.z; Bs[0][akx + 3][arow] = b4.w;
    __syncthreads();

    const int ntiles = HD >> 3;  // 32
    for (int t = 0; t < ntiles; ++t) {
        const int cur = t & 1;
        if (t + 1 < ntiles) {
            a4 = *(const float4*)(aPtr + (t + 1) * 8);
            b4 = *(const float4*)(bPtr + (t + 1) * 8);
        }
        #pragma unroll
        for (int kk = 0; kk < 8; kk++) {
            float4 A0 = *(const float4*)&As[cur][kk][ty * 8];
            float4 A1 = *(const float4*)&As[cur][kk][ty * 8 + 4];
            float4 B0 = *(const float4*)&Bs[cur][kk][tx * 8];
            float4 B1 = *(const float4*)&Bs[cur][kk][tx * 8 + 4];
            float ar[8] = {A0.x, A0.y, A0.z, A0.w, A1.x, A1.y, A1.z, A1.w};
            float br[8] = {B0.x, B0.y, B0.z, B0.w, B1.x, B1.y, B1.z, B1.w};
            #pragma unroll
            for (int i = 0; i < 8; i++)
                #pragma unroll
                for (int j = 0; j < 8; j++)
                    acc[i][j] = fmaf(ar[i], br[j], acc[i][j]);
        }
        if (t + 1 < ntiles) {
            const int nxt = cur ^ 1;
            As[nxt][akx + 0][arow] = a4.x; As[nxt][akx + 1][arow] = a4.y;
            As[nxt][akx + 2][arow] = a4.z; As[nxt][akx + 3][arow] = a4.w;
            Bs[nxt][akx + 0][arow] = b4.x; Bs[nxt][akx + 1][arow] = b4.y;
            Bs[nxt][akx + 2][arow] = b4.z; Bs[nxt][akx + 3][arow] = b4.w;
        }
        __syncthreads();
    }

    const int row = rowBase + ty * 8;
    const int col = colBase + tx * 8;
    #pragma unroll
    for (int i = 0; i < 8; i++) {
        float4 o0 = make_float4(acc[i][0], acc[i][1], acc[i][2], acc[i][3]);
        float4 o1 = make_float4(acc[i][4], acc[i][5], acc[i][6], acc[i][7]);
        *(float4*)&g_sim[(size_t)(row + i) * NN + col]     = o0;
        *(float4*)&g_sim[(size_t)(row + i) * NN + col + 4] = o1;
    }
}

// ---------------------------------------------------------------------------
// Top-16 per row + threshold + zero-fill + scatter. One block (256 thr) per row.
// Keys pack (order-transformed float, ~idx) into u64 so max == jax top_k order
// (lower index wins ties). Diagonal excluded via sentinel below -1.
// ---------------------------------------------------------------------------
__global__ __launch_bounds__(256)
void topk_kernel(float* __restrict__ out)
{
    const int row = blockIdx.x;
    const int tid = threadIdx.x;

    __shared__ unsigned long long warpKey[8];
    __shared__ unsigned long long topKeys[16];
    __shared__ unsigned long long winShared;
    __shared__ float s_keep;

    // zero-fill output row (d_out is poisoned)
    float4 z = make_float4(0.f, 0.f, 0.f, 0.f);
    float4* orow = (float4*)(out + (size_t)row * NN);
    #pragma unroll
    for (int i = 0; i < 8; i++) orow[tid + i * 256] = z;

    // load row, build sortable keys
    unsigned long long keys[32];
    const float* srow = g_sim + (size_t)row * NN;
    #pragma unroll
    for (int j = 0; j < 32; j++) {
        const int c = tid + j * 256;
        float v = srow[c];
        if (c == row) v = -2.0f;  // below min cosine; never selected
        unsigned s = __float_as_uint(v);
        unsigned u = s ^ ((unsigned)((int)s >> 31) | 0x80000000u);
        keys[j] = ((unsigned long long)u << 32) | (unsigned)(~c);
    }

    unsigned long long lbest = 0ULL;
    #pragma unroll
    for (int j = 0; j < 32; j++) if (keys[j] > lbest) lbest = keys[j];

    for (int it = 0; it < 16; ++it) {
        unsigned long long k = lbest;
        #pragma unroll
        for (int off = 16; off > 0; off >>= 1) {
            unsigned long long o = __shfl_down_sync(0xffffffffu, k, off);
            if (o > k) k = o;
        }
        if ((tid & 31) == 0) warpKey[tid >> 5] = k;
        __syncthreads();
        if (tid < 32) {
            unsigned long long kk2 = (tid < 8) ? warpKey[tid] : 0ULL;
            #pragma unroll
            for (int off = 4; off > 0; off >>= 1) {
                unsigned long long o = __shfl_down_sync(0xffffffffu, kk2, off);
                if (o > kk2) kk2 = o;
            }
            if (tid == 0) { topKeys[it] = kk2; winShared = kk2; }
        }
        __syncthreads();
        const unsigned long long win = winShared;
        if (lbest == win) {  // exactly one thread owns the winner (idx is unique)
            #pragma unroll
            for (int j = 0; j < 32; j++) if (keys[j] == win) keys[j] = 0ULL;
            lbest = 0ULL;
            #pragma unroll
            for (int j = 0; j < 32; j++) if (keys[j] > lbest) lbest = keys[j];
        }
    }
    __syncthreads();

    if (tid == 0) {
        float sum = 0.0f;
        #pragma unroll
        for (int it = 0; it < 16; ++it) {
            unsigned u = (unsigned)(topKeys[it] >> 32);
            unsigned s = (u & 0x80000000u) ? (u ^ 0x80000000u) : ~u;
            sum += __uint_as_float(s);
        }
        s_keep = (sum / 16.0f > 0.5f) ? 1.0f : 0.0f;
    }
    __syncthreads();

    if (tid < 16) {
        const unsigned long long k = topKeys[tid];
        unsigned u = (unsigned)(k >> 32);
        unsigned s = (u & 0x80000000u) ? (u ^ 0x80000000u) : ~u;
        const int c = (int)(~(unsigned)(k & 0xffffffffu));
        out[(size_t)row * NN + c] = __uint_as_float(s) * s_keep;
    }
}

// ---------------------------------------------------------------------------
extern "C" void kernel_launch(void* const* d_in, const int* in_sizes, int n_in,
                              void* d_out, int out_size)
{
    const float* x_img = (const float*)d_in[0];
    const float* W_img = (const float*)d_in[1];
    const float* b_img = (const float*)d_in[2];
    const float* x_txt = (const float*)d_in[3];
    const float* W_txt = (const float*)d_in[4];
    const float* b_txt = (const float*)d_in[5];
    const float* x_aud = (const float*)d_in[6];
    const float* W_aud = (const float*)d_in[7];
    const float* b_aud = (const float*)d_in[8];
    float* out = (float*)d_out;

    enc_kernel<<<dim3(2, 64), 256>>>(x_img, W_img, b_img,
                                     x_txt, W_txt, b_txt,
                                     x_aud, W_aud, b_aud);
    norm_kernel<<<1024, 256>>>();
    sim_kernel<<<dim3(64, 64), 256>>>();
    topk_kernel<<<NN, 256>>>(out);
}

// round 2
// speedup vs baseline: 1.3053x; 1.3053x over previous
#include <cuda_runtime.h>
#include <math.h>

#define NN 8192
#define HD 256

typedef unsigned long long u64;

// Scratch (device globals: allocation-free rule).
static __device__ float g_fused[NN * HD];                 // 8 MB
static __device__ float g_hn[NN * HD];                    // 8 MB
static __device__ float g_sim[(size_t)NN * NN];           // 256 MB

// ---- packed f32x2 helpers (FFMA2 path, PTX-only) ---------------------------
__device__ __forceinline__ void fma2(u64 &d, u64 a, u64 b) {
    asm("fma.rn.f32x2 %0, %1, %2, %3;" : "=l"(d) : "l"(a), "l"(b), "l"(d));
}
__device__ __forceinline__ u64 dup2(float x) {
    u64 r; asm("mov.b64 %0, {%1, %1};" : "=l"(r) : "f"(x)); return r;
}
__device__ __forceinline__ void unpack2(u64 v, float &lo, float &hi) {
    asm("mov.b64 {%0, %1}, %2;" : "=f"(lo), "=f"(hi) : "l"(v));
}

// ---------------------------------------------------------------------------
// Encoder: one block computes a 128x128 tile of fused = sum_m relu(X_m W_m + b_m)
// (the /3 is deferred to the normalize kernel). 256 threads, 8x8 per thread,
// BK=8, double-buffered smem, packed-FFMA2 inner loop.
// ---------------------------------------------------------------------------
__device__ __forceinline__ void enc_gemm_one(
    float (&total)[8][8],
    const float* __restrict__ X, const float* __restrict__ W,
    const float* __restrict__ bias,
    int K, int rowBase, int colBase, int tid,
    float (*As)[8][128], float (*Bs)[8][128])
{
    const int arow = tid >> 1;          // 0..127
    const int akx  = (tid & 1) * 4;     // 0 or 4
    const int bk   = tid >> 5;          // 0..7
    const int bn   = (tid & 31) * 4;    // 0..124
    const int ty   = tid >> 4;          // 0..15
    const int tx   = tid & 15;          // 0..15

    const float* aPtr = X + (size_t)(rowBase + arow) * K + akx;
    const float* bPtr = W + (size_t)bk * HD + colBase + bn;

    u64 acc2[4][8];                     // row-pairs (2i,2i+1) x 8 cols
    #pragma unroll
    for (int i = 0; i < 4; i++)
        #pragma unroll
        for (int j = 0; j < 8; j++) acc2[i][j] = 0ULL;

    const int ntiles = K >> 3;

    float4 a4 = *(const float4*)aPtr;
    float4 b4 = *(const float4*)bPtr;
    As[0][akx + 0][arow] = a4.x; As[0][akx + 1][arow] = a4.y;
    As[0][akx + 2][arow] = a4.z; As[0][akx + 3][arow] = a4.w;
    *(float4*)&Bs[0][bk][bn] = b4;
    __syncthreads();

    for (int t = 0; t < ntiles; ++t) {
        const int cur = t & 1;
        if (t + 1 < ntiles) {
            a4 = *(const float4*)(aPtr + (t + 1) * 8);
            b4 = *(const float4*)(bPtr + (size_t)(t + 1) * 8 * HD);
        }
        #pragma unroll
        for (int kk = 0; kk < 8; kk++) {
            ulonglong2 a01 = *(const ulonglong2*)&As[cur][kk][ty * 8];
            ulonglong2 a23 = *(const ulonglong2*)&As[cur][kk][ty * 8 + 4];
            float4 B0 = *(const float4*)&Bs[cur][kk][tx * 8];
            float4 B1 = *(const float4*)&Bs[cur][kk][tx * 8 + 4];
            u64 brd[8];
            brd[0] = dup2(B0.x); brd[1] = dup2(B0.y);
            brd[2] = dup2(B0.z); brd[3] = dup2(B0.w);
            brd[4] = dup2(B1.x); brd[5] = dup2(B1.y);
            brd[6] = dup2(B1.z); brd[7] = dup2(B1.w);
            #pragma unroll
            for (int j = 0; j < 8; j++) {
                fma2(acc2[0][j], a01.x, brd[j]);
                fma2(acc2[1][j], a01.y, brd[j]);
                fma2(acc2[2][j], a23.x, brd[j]);
                fma2(acc2[3][j], a23.y, brd[j]);
            }
        }
        if (t + 1 < ntiles) {
            const int nxt = cur ^ 1;
            As[nxt][akx + 0][arow] = a4.x; As[nxt][akx + 1][arow] = a4.y;
            As[nxt][akx + 2][arow] = a4.z; As[nxt][akx + 3][arow] = a4.w;
            *(float4*)&Bs[nxt][bk][bn] = b4;
        }
        __syncthreads();
    }

    const int col = colBase + tx * 8;
    float bb[8];
    #pragma unroll
    for (int j = 0; j < 8; j++) bb[j] = bias[col + j];
    #pragma unroll
    for (int i2 = 0; i2 < 4; i2++)
        #pragma unroll
        for (int j = 0; j < 8; j++) {
            float lo, hi;
            unpack2(acc2[i2][j], lo, hi);
            total[2 * i2 + 0][j] += fmaxf(lo + bb[j], 0.0f);
            total[2 * i2 + 1][j] += fmaxf(hi + bb[j], 0.0f);
        }
}

__global__ __launch_bounds__(256, 1)
void enc_kernel(const float* __restrict__ X0, const float* __restrict__ W0, const float* __restrict__ b0,
                const float* __restrict__ X1, const float* __restrict__ W1, const float* __restrict__ b1,
                const float* __restrict__ X2, const float* __restrict__ W2, const float* __restrict__ b2)
{
    __shared__ __align__(16) float As[2][8][128];
    __shared__ __align__(16) float Bs[2][8][128];
    const int tid = threadIdx.x;
    const int rowBase = blockIdx.y * 128;
    const int colBase = blockIdx.x * 128;

    float total[8][8];
    #pragma unroll
    for (int i = 0; i < 8; i++)
        #pragma unroll
        for (int j = 0; j < 8; j++) total[i][j] = 0.0f;

    // order matches reference: image + text + audio (left-associated)
    enc_gemm_one(total, X0, W0, b0, 1024, rowBase, colBase, tid, As, Bs);
    enc_gemm_one(total, X1, W1, b1,  768, rowBase, colBase, tid, As, Bs);
    enc_gemm_one(total, X2, W2, b2,  512, rowBase, colBase, tid, As, Bs);

    const int ty = tid >> 4, tx = tid & 15;
    const int row = rowBase + ty * 8;
    const int col = colBase + tx * 8;
    #pragma unroll
    for (int i = 0; i < 8; i++) {
        float4 o0 = make_float4(total[i][0], total[i][1], total[i][2], total[i][3]);
        float4 o1 = make_float4(total[i][4], total[i][5], total[i][6], total[i][7]);
        *(float4*)&g_fused[(size_t)(row + i) * HD + col]     = o0;
        *(float4*)&g_fused[(size_t)(row + i) * HD + col + 4] = o1;
    }
}

// ---------------------------------------------------------------------------
// Row normalize: hn = (fused/3) / (||fused/3|| + 1e-8). One warp per row.
// ---------------------------------------------------------------------------
__global__ void norm_kernel()
{
    const int tid  = threadIdx.x;
    const int lane = tid & 31;
    const int warp = tid >> 5;
    const int row  = blockIdx.x * 8 + warp;

    const float* fr = g_fused + (size_t)row * HD;
    float v[8];
    float ss = 0.0f;
    #pragma unroll
    for (int i = 0; i < 8; i++) {
        float x = fr[lane + i * 32] / 3.0f;
        v[i] = x;
        ss += x * x;
    }
    #pragma unroll
    for (int off = 16; off > 0; off >>= 1)
        ss += __shfl_xor_sync(0xffffffffu, ss, off);
    const float den = sqrtf(ss) + 1e-8f;
    #pragma unroll
    for (int i = 0; i < 8; i++)
        g_hn[(size_t)row * HD + lane + i * 32] = v[i] / den;
}

// ---------------------------------------------------------------------------
// sim = hn @ hn^T, symmetric: compute only tiles by<=bx, mirror-store the
// off-diagonal ones. Packed-FFMA2 inner loop.
// ---------------------------------------------------------------------------
__global__ __launch_bounds__(256, 2)
void sim_kernel()
{
    const int bx = blockIdx.x, by = blockIdx.y;
    if (by > bx) return;                       // upper triangle only

    __shared__ __align__(16) float As[2][8][128];
    __shared__ __align__(16) float Bs[2][8][128];
    const int tid = threadIdx.x;
    const int rowBase = by * 128;
    const int colBase = bx * 128;
    const int arow = tid >> 1;
    const int akx  = (tid & 1) * 4;
    const int ty   = tid >> 4;
    const int tx   = tid & 15;

    const float* aPtr = g_hn + (size_t)(rowBase + arow) * HD + akx;
    const float* bPtr = g_hn + (size_t)(colBase + arow) * HD + akx;

    u64 acc2[4][8];
    #pragma unroll
    for (int i = 0; i < 4; i++)
        #pragma unroll
        for (int j = 0; j < 8; j++) acc2[i][j] = 0ULL;

    float4 a4 = *(const float4*)aPtr;
    float4 b4 = *(const float4*)bPtr;
    As[0][akx + 0][arow] = a4.x; As[0][akx + 1][arow] = a4.y;
    As[0][akx + 2][arow] = a4.z; As[0][akx + 3][arow] = a4.w;
    Bs[0][akx + 0][arow] = b4.x; Bs[0][akx + 1][arow] = b4.y;
    Bs[0][akx + 2][arow] = b4.z; Bs[0][akx + 3][arow] = b4.w;
    __syncthreads();

    const int ntiles = HD >> 3;  // 32
    for (int t = 0; t < ntiles; ++t) {
        const int cur = t & 1;
        if (t + 1 < ntiles) {
            a4 = *(const float4*)(aPtr + (t + 1) * 8);
            b4 = *(const float4*)(bPtr + (t + 1) * 8);
        }
        #pragma unroll
        for (int kk = 0; kk < 8; kk++) {
            ulonglong2 a01 = *(const ulonglong2*)&As[cur][kk][ty * 8];
            ulonglong2 a23 = *(const ulonglong2*)&As[cur][kk][ty * 8 + 4];
            float4 B0 = *(const float4*)&Bs[cur][kk][tx * 8];
            float4 B1 = *(const float4*)&Bs[cur][kk][tx * 8 + 4];
            u64 brd[8];
            brd[0] = dup2(B0.x); brd[1] = dup2(B0.y);
            brd[2] = dup2(B0.z); brd[3] = dup2(B0.w);
            brd[4] = dup2(B1.x); brd[5] = dup2(B1.y);
            brd[6] = dup2(B1.z); brd[7] = dup2(B1.w);
            #pragma unroll
            for (int j = 0; j < 8; j++) {
                fma2(acc2[0][j], a01.x, brd[j]);
                fma2(acc2[1][j], a01.y, brd[j]);
                fma2(acc2[2][j], a23.x, brd[j]);
                fma2(acc2[3][j], a23.y, brd[j]);
            }
        }
        if (t + 1 < ntiles) {
            const int nxt = cur ^ 1;
            As[nxt][akx + 0][arow] = a4.x; As[nxt][akx + 1][arow] = a4.y;
            As[nxt][akx + 2][arow] = a4.z; As[nxt][akx + 3][arow] = a4.w;
            Bs[nxt][akx + 0][arow] = b4.x; Bs[nxt][akx + 1][arow] = b4.y;
            Bs[nxt][akx + 2][arow] = b4.z; Bs[nxt][akx + 3][arow] = b4.w;
        }
        __syncthreads();
    }

    float c[8][8];
    #pragma unroll
    for (int i2 = 0; i2 < 4; i2++)
        #pragma unroll
        for (int j = 0; j < 8; j++)
            unpack2(acc2[i2][j], c[2 * i2][j], c[2 * i2 + 1][j]);

    const int row = rowBase + ty * 8;
    const int col = colBase + tx * 8;
    #pragma unroll
    for (int i = 0; i < 8; i++) {
        float4 o0 = make_float4(c[i][0], c[i][1], c[i][2], c[i][3]);
        float4 o1 = make_float4(c[i][4], c[i][5], c[i][6], c[i][7]);
        *(float4*)&g_sim[(size_t)(row + i) * NN + col]     = o0;
        *(float4*)&g_sim[(size_t)(row + i) * NN + col + 4] = o1;
    }
    if (by != bx) {  // mirror: transposed tile
        #pragma unroll
        for (int j = 0; j < 8; j++) {
            float4 t0 = make_float4(c[0][j], c[1][j], c[2][j], c[3][j]);
            float4 t1 = make_float4(c[4][j], c[5][j], c[6][j], c[7][j]);
            size_t base = (size_t)(col + j) * NN + row;
            *(float4*)&g_sim[base]     = t0;
            *(float4*)&g_sim[base + 4] = t1;
        }
    }
}

// ---------------------------------------------------------------------------
// Top-16 per row + threshold + zero-fill + scatter. One block (256 thr) per row.
// Warp-local top-16 via bfly shuffles (no block barriers), then single-warp
// merge of 8x16 candidates. Keys pack (order-transformed float, ~idx) so u64
// max == jax top_k order (desc value, lower index wins ties).
// ---------------------------------------------------------------------------
__device__ __forceinline__ float key_val(u64 k) {
    unsigned u = (unsigned)(k >> 32);
    unsigned s = (u & 0x80000000u) ? (u ^ 0x80000000u) : ~u;
    return __uint_as_float(s);
}

__global__ __launch_bounds__(256)
void topk_kernel(float* __restrict__ out)
{
    const int row  = blockIdx.x;
    const int tid  = threadIdx.x;
    const int lane = tid & 31;
    const int wid  = tid >> 5;

    __shared__ u64 sTop[8][16];
    __shared__ u64 sFinal[16];
    __shared__ float s_keep;

    // zero-fill output row (d_out is poisoned)
    float4 z = make_float4(0.f, 0.f, 0.f, 0.f);
    float4* orow = (float4*)(out + (size_t)row * NN);
    #pragma unroll
    for (int i = 0; i < 8; i++) orow[tid + i * 256] = z;

    // load row, build sortable keys
    u64 keys[32];
    const float* srow = g_sim + (size_t)row * NN;
    #pragma unroll
    for (int j = 0; j < 32; j++) {
        const int cidx = tid + j * 256;
        float v = srow[cidx];
        if (cidx == row) v = -2.0f;  // below min cosine; never selected
        unsigned s = __float_as_uint(v);
        unsigned u = s ^ ((unsigned)((int)s >> 31) | 0x80000000u);
        keys[j] = ((u64)u << 32) | (unsigned)(~cidx);
    }

    // group maxima (4 groups of 8) for cheap removal
    u64 gm[4];
    #pragma unroll
    for (int g = 0; g < 4; g++) {
        u64 m = 0ULL;
        #pragma unroll
        for (int j = 0; j < 8; j++) if (keys[g * 8 + j] > m) m = keys[g * 8 + j];
        gm[g] = m;
    }
    u64 lmax = gm[0];
    if (gm[1] > lmax) lmax = gm[1];
    if (gm[2] > lmax) lmax = gm[2];
    if (gm[3] > lmax) lmax = gm[3];

    // warp-local top-16 (no block barriers)
    #pragma unroll 1
    for (int it = 0; it < 16; ++it) {
        u64 w = lmax;
        #pragma unroll
        for (int off = 16; off > 0; off >>= 1) {
            u64 o = __shfl_xor_sync(0xffffffffu, w, off);
            if (o > w) w = o;
        }
        if (lane == 0) sTop[wid][it] = w;
        if (lmax == w) {  // unique owner (indices distinct)
            #pragma unroll
            for (int g = 0; g < 4; g++) {
                if (gm[g] == w) {
                    u64 nm = 0ULL;
                    #pragma unroll
                    for (int j = 0; j < 8; j++) {
                        if (keys[g * 8 + j] == w) keys[g * 8 + j] = 0ULL;
                        else if (keys[g * 8 + j] > nm) nm = keys[g * 8 + j];
                    }
                    gm[g] = nm;
                }
            }
            lmax = gm[0];
            if (gm[1] > lmax) lmax = gm[1];
            if (gm[2] > lmax) lmax = gm[2];
            if (gm[3] > lmax) lmax = gm[3];
        }
    }
    __syncthreads();

    // single-warp merge of 128 candidates
    if (wid == 0) {
        u64 cand[4];
        #pragma unroll
        for (int q = 0; q < 4; q++) {
            const int idx = lane * 4 + q;
            cand[q] = sTop[idx >> 4][idx & 15];
        }
        u64 lm = cand[0];
        if (cand[1] > lm) lm = cand[1];
        if (cand[2] > lm) lm = cand[2];
        if (cand[3] > lm) lm = cand[3];
        #pragma unroll 1
        for (int it = 0; it < 16; ++it) {
            u64 w = lm;
            #pragma unroll
            for (int off = 16; off > 0; off >>= 1) {
                u64 o = __shfl_xor_sync(0xffffffffu, w, off);
                if (o > w) w = o;
            }
            if (lane == 0) sFinal[it] = w;
            if (lm == w) {
                u64 nm = 0ULL;
                #pragma unroll
                for (int q = 0; q < 4; q++) {
                    if (cand[q] == w) cand[q] = 0ULL;
                    else if (cand[q] > nm) nm = cand[q];
                }
                lm = nm;
            }
        }
        if (lane == 0) {
            float sum = 0.0f;
            #pragma unroll
            for (int it = 0; it < 16; ++it) sum += key_val(sFinal[it]);
            s_keep = (sum / 16.0f > 0.5f) ? 1.0f : 0.0f;
        }
    }
    __syncthreads();

    if (tid < 16) {
        const u64 k = sFinal[tid];
        const int cidx = (int)(~(unsigned)(k & 0xffffffffu));
        out[(size_t)row * NN + cidx] = key_val(k) * s_keep;
    }
}

// ---------------------------------------------------------------------------
extern "C" void kernel_launch(void* const* d_in, const int* in_sizes, int n_in,
                              void* d_out, int out_size)
{
    const float* x_img = (const float*)d_in[0];
    const float* W_img = (const float*)d_in[1];
    const float* b_img = (const float*)d_in[2];
    const float* x_txt = (const float*)d_in[3];
    const float* W_txt = (const float*)d_in[4];
    const float* b_txt = (const float*)d_in[5];
    const float* x_aud = (const float*)d_in[6];
    const float* W_aud = (const float*)d_in[7];
    const float* b_aud = (const float*)d_in[8];
    float* out = (float*)d_out;

    enc_kernel<<<dim3(2, 64), 256>>>(x_img, W_img, b_img,
                                     x_txt, W_txt, b_txt,
                                     x_aud, W_aud, b_aud);
    norm_kernel<<<1024, 256>>>();
    sim_kernel<<<dim3(64, 64), 256>>>();
    topk_kernel<<<NN, 256>>>(out);
}

// round 3
// speedup vs baseline: 1.5580x; 1.1935x over previous
#include <cuda_runtime.h>
#include <math.h>

#define NN 8192
#define HD 256

typedef unsigned long long u64;

// Scratch (device globals: allocation-free rule).
static __device__ float g_fused[NN * HD];                 // 8 MB
static __device__ float g_hn[NN * HD];                    // 8 MB
static __device__ float g_sim[(size_t)NN * NN];           // 256 MB

// ---- packed f32x2 helpers (FFMA2 path, PTX-only) ---------------------------
__device__ __forceinline__ void fma2(u64 &d, u64 a, u64 b) {
    asm("fma.rn.f32x2 %0, %1, %2, %3;" : "=l"(d) : "l"(a), "l"(b), "l"(d));
}
__device__ __forceinline__ u64 dup2(float x) {
    u64 r; asm("mov.b64 %0, {%1, %1};" : "=l"(r) : "f"(x)); return r;
}
__device__ __forceinline__ void unpack2(u64 v, float &lo, float &hi) {
    asm("mov.b64 {%0, %1}, %2;" : "=f"(lo), "=f"(hi) : "l"(v));
}

// ---------------------------------------------------------------------------
// Encoder: one block computes a 128x128 tile of fused = sum_m relu(X_m W_m + b_m)
// ---------------------------------------------------------------------------
__device__ __forceinline__ void enc_gemm_one(
    float (&total)[8][8],
    const float* __restrict__ X, const float* __restrict__ W,
    const float* __restrict__ bias,
    int K, int rowBase, int colBase, int tid,
    float (*As)[8][128], float (*Bs)[8][128])
{
    const int arow = tid >> 1;
    const int akx  = (tid & 1) * 4;
    const int bk   = tid >> 5;
    const int bn   = (tid & 31) * 4;
    const int ty   = tid >> 4;
    const int tx   = tid & 15;

    const float* aPtr = X + (size_t)(rowBase + arow) * K + akx;
    const float* bPtr = W + (size_t)bk * HD + colBase + bn;

    u64 acc2[4][8];
    #pragma unroll
    for (int i = 0; i < 4; i++)
        #pragma unroll
        for (int j = 0; j < 8; j++) acc2[i][j] = 0ULL;

    const int ntiles = K >> 3;

    float4 a4 = *(const float4*)aPtr;
    float4 b4 = *(const float4*)bPtr;
    As[0][akx + 0][arow] = a4.x; As[0][akx + 1][arow] = a4.y;
    As[0][akx + 2][arow] = a4.z; As[0][akx + 3][arow] = a4.w;
    *(float4*)&Bs[0][bk][bn] = b4;
    __syncthreads();

    for (int t = 0; t < ntiles; ++t) {
        const int cur = t & 1;
        if (t + 1 < ntiles) {
            a4 = *(const float4*)(aPtr + (t + 1) * 8);
            b4 = *(const float4*)(bPtr + (size_t)(t + 1) * 8 * HD);
        }
        #pragma unroll
        for (int kk = 0; kk < 8; kk++) {
            ulonglong2 a01 = *(const ulonglong2*)&As[cur][kk][ty * 8];
            ulonglong2 a23 = *(const ulonglong2*)&As[cur][kk][ty * 8 + 4];
            float4 B0 = *(const float4*)&Bs[cur][kk][tx * 8];
            float4 B1 = *(const float4*)&Bs[cur][kk][tx * 8 + 4];
            u64 brd[8];
            brd[0] = dup2(B0.x); brd[1] = dup2(B0.y);
            brd[2] = dup2(B0.z); brd[3] = dup2(B0.w);
            brd[4] = dup2(B1.x); brd[5] = dup2(B1.y);
            brd[6] = dup2(B1.z); brd[7] = dup2(B1.w);
            #pragma unroll
            for (int j = 0; j < 8; j++) {
                fma2(acc2[0][j], a01.x, brd[j]);
                fma2(acc2[1][j], a01.y, brd[j]);
                fma2(acc2[2][j], a23.x, brd[j]);
                fma2(acc2[3][j], a23.y, brd[j]);
            }
        }
        if (t + 1 < ntiles) {
            const int nxt = cur ^ 1;
            As[nxt][akx + 0][arow] = a4.x; As[nxt][akx + 1][arow] = a4.y;
            As[nxt][akx + 2][arow] = a4.z; As[nxt][akx + 3][arow] = a4.w;
            *(float4*)&Bs[nxt][bk][bn] = b4;
        }
        __syncthreads();
    }

    const int col = colBase + tx * 8;
    float bb[8];
    #pragma unroll
    for (int j = 0; j < 8; j++) bb[j] = bias[col + j];
    #pragma unroll
    for (int i2 = 0; i2 < 4; i2++)
        #pragma unroll
        for (int j = 0; j < 8; j++) {
            float lo, hi;
            unpack2(acc2[i2][j], lo, hi);
            total[2 * i2 + 0][j] += fmaxf(lo + bb[j], 0.0f);
            total[2 * i2 + 1][j] += fmaxf(hi + bb[j], 0.0f);
        }
}

__global__ __launch_bounds__(256, 1)
void enc_kernel(const float* __restrict__ X0, const float* __restrict__ W0, const float* __restrict__ b0,
                const float* __restrict__ X1, const float* __restrict__ W1, const float* __restrict__ b1,
                const float* __restrict__ X2, const float* __restrict__ W2, const float* __restrict__ b2)
{
    __shared__ __align__(16) float As[2][8][128];
    __shared__ __align__(16) float Bs[2][8][128];
    const int tid = threadIdx.x;
    const int rowBase = blockIdx.y * 128;
    const int colBase = blockIdx.x * 128;

    float total[8][8];
    #pragma unroll
    for (int i = 0; i < 8; i++)
        #pragma unroll
        for (int j = 0; j < 8; j++) total[i][j] = 0.0f;

    enc_gemm_one(total, X0, W0, b0, 1024, rowBase, colBase, tid, As, Bs);
    enc_gemm_one(total, X1, W1, b1,  768, rowBase, colBase, tid, As, Bs);
    enc_gemm_one(total, X2, W2, b2,  512, rowBase, colBase, tid, As, Bs);

    const int ty = tid >> 4, tx = tid & 15;
    const int row = rowBase + ty * 8;
    const int col = colBase + tx * 8;
    #pragma unroll
    for (int i = 0; i < 8; i++) {
        float4 o0 = make_float4(total[i][0], total[i][1], total[i][2], total[i][3]);
        float4 o1 = make_float4(total[i][4], total[i][5], total[i][6], total[i][7]);
        *(float4*)&g_fused[(size_t)(row + i) * HD + col]     = o0;
        *(float4*)&g_fused[(size_t)(row + i) * HD + col + 4] = o1;
    }
}

// ---------------------------------------------------------------------------
// Row normalize: hn = (fused/3) / (||fused/3|| + 1e-8). One warp per row.
// ---------------------------------------------------------------------------
__global__ void norm_kernel()
{
    const int tid  = threadIdx.x;
    const int lane = tid & 31;
    const int warp = tid >> 5;
    const int row  = blockIdx.x * 8 + warp;

    const float* fr = g_fused + (size_t)row * HD;
    float v[8];
    float ss = 0.0f;
    #pragma unroll
    for (int i = 0; i < 8; i++) {
        float x = fr[lane + i * 32] / 3.0f;
        v[i] = x;
        ss += x * x;
    }
    #pragma unroll
    for (int off = 16; off > 0; off >>= 1)
        ss += __shfl_xor_sync(0xffffffffu, ss, off);
    const float den = sqrtf(ss) + 1e-8f;
    #pragma unroll
    for (int i = 0; i < 8; i++)
        g_hn[(size_t)row * HD + lane + i * 32] = v[i] / den;
}

// ---------------------------------------------------------------------------
// sim = hn @ hn^T, symmetric: compute only tiles by<=bx, mirror-store.
// ---------------------------------------------------------------------------
__global__ __launch_bounds__(256, 2)
void sim_kernel()
{
    const int bx = blockIdx.x, by = blockIdx.y;
    if (by > bx) return;

    __shared__ __align__(16) float As[2][8][128];
    __shared__ __align__(16) float Bs[2][8][128];
    const int tid = threadIdx.x;
    const int rowBase = by * 128;
    const int colBase = bx * 128;
    const int arow = tid >> 1;
    const int akx  = (tid & 1) * 4;
    const int ty   = tid >> 4;
    const int tx   = tid & 15;

    const float* aPtr = g_hn + (size_t)(rowBase + arow) * HD + akx;
    const float* bPtr = g_hn + (size_t)(colBase + arow) * HD + akx;

    u64 acc2[4][8];
    #pragma unroll
    for (int i = 0; i < 4; i++)
        #pragma unroll
        for (int j = 0; j < 8; j++) acc2[i][j] = 0ULL;

    float4 a4 = *(const float4*)aPtr;
    float4 b4 = *(const float4*)bPtr;
    As[0][akx + 0][arow] = a4.x; As[0][akx + 1][arow] = a4.y;
    As[0][akx + 2][arow] = a4.z; As[0][akx + 3][arow] = a4.w;
    Bs[0][akx + 0][arow] = b4.x; Bs[0][akx + 1][arow] = b4.y;
    Bs[0][akx + 2][arow] = b4.z; Bs[0][akx + 3][arow] = b4.w;
    __syncthreads();

    const int ntiles = HD >> 3;
    for (int t = 0; t < ntiles; ++t) {
        const int cur = t & 1;
        if (t + 1 < ntiles) {
            a4 = *(const float4*)(aPtr + (t + 1) * 8);
            b4 = *(const float4*)(bPtr + (t + 1) * 8);
        }
        #pragma unroll
        for (int kk = 0; kk < 8; kk++) {
            ulonglong2 a01 = *(const ulonglong2*)&As[cur][kk][ty * 8];
            ulonglong2 a23 = *(const ulonglong2*)&As[cur][kk][ty * 8 + 4];
            float4 B0 = *(const float4*)&Bs[cur][kk][tx * 8];
            float4 B1 = *(const float4*)&Bs[cur][kk][tx * 8 + 4];
            u64 brd[8];
            brd[0] = dup2(B0.x); brd[1] = dup2(B0.y);
            brd[2] = dup2(B0.z); brd[3] = dup2(B0.w);
            brd[4] = dup2(B1.x); brd[5] = dup2(B1.y);
            brd[6] = dup2(B1.z); brd[7] = dup2(B1.w);
            #pragma unroll
            for (int j = 0; j < 8; j++) {
                fma2(acc2[0][j], a01.x, brd[j]);
                fma2(acc2[1][j], a01.y, brd[j]);
                fma2(acc2[2][j], a23.x, brd[j]);
                fma2(acc2[3][j], a23.y, brd[j]);
            }
        }
        if (t + 1 < ntiles) {
            const int nxt = cur ^ 1;
            As[nxt][akx + 0][arow] = a4.x; As[nxt][akx + 1][arow] = a4.y;
            As[nxt][akx + 2][arow] = a4.z; As[nxt][akx + 3][arow] = a4.w;
            Bs[nxt][akx + 0][arow] = b4.x; Bs[nxt][akx + 1][arow] = b4.y;
            Bs[nxt][akx + 2][arow] = b4.z; Bs[nxt][akx + 3][arow] = b4.w;
        }
        __syncthreads();
    }

    float c[8][8];
    #pragma unroll
    for (int i2 = 0; i2 < 4; i2++)
        #pragma unroll
        for (int j = 0; j < 8; j++)
            unpack2(acc2[i2][j], c[2 * i2][j], c[2 * i2 + 1][j]);

    const int row = rowBase + ty * 8;
    const int col = colBase + tx * 8;
    #pragma unroll
    for (int i = 0; i < 8; i++) {
        float4 o0 = make_float4(c[i][0], c[i][1], c[i][2], c[i][3]);
        float4 o1 = make_float4(c[i][4], c[i][5], c[i][6], c[i][7]);
        *(float4*)&g_sim[(size_t)(row + i) * NN + col]     = o0;
        *(float4*)&g_sim[(size_t)(row + i) * NN + col + 4] = o1;
    }
    if (by != bx) {
        #pragma unroll
        for (int j = 0; j < 8; j++) {
            float4 t0 = make_float4(c[0][j], c[1][j], c[2][j], c[3][j]);
            float4 t1 = make_float4(c[4][j], c[5][j], c[6][j], c[7][j]);
            size_t base = (size_t)(col + j) * NN + row;
            *(float4*)&g_sim[base]     = t0;
            *(float4*)&g_sim[base + 4] = t1;
        }
    }
}

// ---------------------------------------------------------------------------
// Top-16 per row: histogram rank-filter + exact selection over few candidates.
// One block (256 thr) per row. Binning clamp(trunc((v+1)*128)) is monotone, so
// all elements in bins < b1 (highest bin with suffix-count >= 16) are provably
// below the top-16. Exact order on candidates: u64 key (desc value, asc index),
// identical to jax top_k tie semantics.
// ---------------------------------------------------------------------------
__device__ __forceinline__ float key_val(u64 k) {
    unsigned u = (unsigned)(k >> 32);
    unsigned s = (u & 0x80000000u) ? (u ^ 0x80000000u) : ~u;
    return __uint_as_float(s);
}
__device__ __forceinline__ int bin_of(float v) {
    int b = (int)((v + 1.0f) * 128.0f);
    return max(0, min(255, b));
}

#define CAND_CAP 2048

__global__ __launch_bounds__(256)
void topk_kernel(float* __restrict__ out)
{
    const int row  = blockIdx.x;
    const int tid  = threadIdx.x;
    const int lane = tid & 31;
    const int wid  = tid >> 5;

    __shared__ unsigned hist[256];
    __shared__ int s_b1;
    __shared__ unsigned candCnt;
    __shared__ u64 candBuf[CAND_CAP];
    __shared__ u64 sFinal[16];
    __shared__ float s_keep;

    // zero-fill output row (d_out is poisoned)
    float4 z = make_float4(0.f, 0.f, 0.f, 0.f);
    float4* orow = (float4*)(out + (size_t)row * NN);
    #pragma unroll
    for (int i = 0; i < 8; i++) orow[tid + i * 256] = z;

    hist[tid] = 0u;
    if (tid == 0) candCnt = 0u;
    __syncthreads();

    // load row (diag -> -2, below all cosines)
    float v[32];
    const float* srow = g_sim + (size_t)row * NN;
    #pragma unroll
    for (int j = 0; j < 32; j++) {
        const int c = tid + j * 256;
        float x = srow[c];
        v[j] = (c == row) ? -2.0f : x;
    }

    // histogram
    #pragma unroll
    for (int j = 0; j < 32; j++)
        atomicAdd(&hist[bin_of(v[j])], 1u);
    __syncthreads();

    // warp 0: find b1 = max bin with suffix_count(b1) >= 16
    if (wid == 0) {
        unsigned h[8];
        unsigned s = 0;
        #pragma unroll
        for (int q = 0; q < 8; q++) { h[q] = hist[lane * 8 + q]; s += h[q]; }
        unsigned suf = s;  // inclusive suffix over lanes
        #pragma unroll
        for (int off = 1; off < 32; off <<= 1) {
            unsigned o = __shfl_down_sync(0xffffffffu, suf, off);
            if (lane + off < 32) suf += o;
        }
        unsigned run = suf - s;  // elems in bins above this lane's range
        int best = -1;
        #pragma unroll
        for (int q = 7; q >= 0; q--) {
            run += h[q];
            if (best < 0 && run >= 16u) best = lane * 8 + q;
        }
        #pragma unroll
        for (int off = 16; off > 0; off >>= 1) {
            int o = __shfl_xor_sync(0xffffffffu, best, off);
            best = max(best, o);
        }
        if (lane == 0) s_b1 = best;
    }
    __syncthreads();
    const int b1 = s_b1;

    // collect candidates (bin >= b1), warp-aggregated append
    #pragma unroll
    for (int j = 0; j < 32; j++) {
        const bool p = (bin_of(v[j]) >= b1);
        const unsigned m = __ballot_sync(0xffffffffu, p);
        if (m == 0u) continue;
        const int leader = __ffs(m) - 1;
        unsigned base = 0;
        if (lane == leader) base = atomicAdd(&candCnt, (unsigned)__popc(m));
        base = __shfl_sync(0xffffffffu, base, leader);
        if (p) {
            const unsigned pos = base + __popc(m & ((1u << lane) - 1u));
            if (pos < CAND_CAP) {
                const int c = tid + j * 256;
                unsigned s = __float_as_uint(v[j]);
                unsigned u = s ^ ((unsigned)((int)s >> 31) | 0x80000000u);
                candBuf[pos] = ((u64)u << 32) | (unsigned)(~c);
            }
        }
    }
    __syncthreads();

    // warp 0: exact top-16 over n candidates (n >= 16 by construction)
    if (wid == 0) {
        const int n = min((int)candCnt, CAND_CAP);
        for (int it = 0; it < 16; ++it) {
            u64 lm = 0ULL;
            for (int i = lane; i < n; i += 32) {
                u64 k = candBuf[i];
                if (k > lm) lm = k;
            }
            u64 w = lm;
            #pragma unroll
            for (int off = 16; off > 0; off >>= 1) {
                u64 o = __shfl_xor_sync(0xffffffffu, w, off);
                if (o > w) w = o;
            }
            if (lane == 0) sFinal[it] = w;
            for (int i = lane; i < n; i += 32)
                if (candBuf[i] == w) candBuf[i] = 0ULL;
        }
        if (lane == 0) {
            float sum = 0.0f;
            #pragma unroll
            for (int it = 0; it < 16; ++it) sum += key_val(sFinal[it]);
            s_keep = (sum / 16.0f > 0.5f) ? 1.0f : 0.0f;
        }
    }
    __syncthreads();

    if (tid < 16) {
        const u64 k = sFinal[tid];
        const int c = (int)(~(unsigned)(k & 0xffffffffu));
        out[(size_t)row * NN + c] = key_val(k) * s_keep;
    }
}

// ---------------------------------------------------------------------------
extern "C" void kernel_launch(void* const* d_in, const int* in_sizes, int n_in,
                              void* d_out, int out_size)
{
    const float* x_img = (const float*)d_in[0];
    const float* W_img = (const float*)d_in[1];
    const float* b_img = (const float*)d_in[2];
    const float* x_txt = (const float*)d_in[3];
    const float* W_txt = (const float*)d_in[4];
    const float* b_txt = (const float*)d_in[5];
    const float* x_aud = (const float*)d_in[6];
    const float* W_aud = (const float*)d_in[7];
    const float* b_aud = (const float*)d_in[8];
    float* out = (float*)d_out;

    enc_kernel<<<dim3(2, 64), 256>>>(x_img, W_img, b_img,
                                     x_txt, W_txt, b_txt,
                                     x_aud, W_aud, b_aud);
    norm_kernel<<<1024, 256>>>();
    sim_kernel<<<dim3(64, 64), 256>>>();
    topk_kernel<<<NN, 256>>>(out);
}